// round 15
// baseline (speedup 1.0000x reference)
#include <cuda_runtime.h>
#include <cstdint>
#include <math.h>

#define T_LEN 2048
#define HID   2048
#define QKVT  8192
#define VTOT  4096
#define NHV   32
#define NHK   16

// ---------------- scratch (device globals; no allocation allowed) ----------------
__device__ float g_mixed[16777216];   // [T, 8192]  qkv-proj out
__device__ float g_conv [16777216];   // [T, 8192]  conv+silu(+l2norm) out
__device__ float g_z    [ 8388608];   // [T, 4096]
__device__ float g_o    [ 8388608];   // [T, 32, 128]
__device__ float g_eg   [NHV*T_LEN];  // transposed: [32][T]
__device__ float g_beta [NHV*T_LEN];  // transposed: [32][T]
// tf32-prerounded operands
__device__ float g_h  [ 4194304];     // [2048, 2048]
__device__ float g_wq [16777216];     // [8192, 2048]
__device__ float g_wz [ 8388608];     // [4096, 2048]
__device__ float g_wo [ 8388608];     // [2048, 4096]

// ---------------- helpers ----------------
__device__ __forceinline__ float tf32r(float x){
    uint32_t u; asm("cvt.rna.tf32.f32 %0, %1;" : "=r"(u) : "f"(x));
    return __uint_as_float(u);
}
__device__ __forceinline__ void mma_tf32(float* c, const uint32_t* a, const uint32_t* b){
    asm volatile("mma.sync.aligned.m16n8k8.row.col.f32.tf32.tf32.f32 "
        "{%0,%1,%2,%3}, {%4,%5,%6,%7}, {%8,%9}, {%0,%1,%2,%3};\n"
        : "+f"(c[0]), "+f"(c[1]), "+f"(c[2]), "+f"(c[3])
        : "r"(a[0]), "r"(a[1]), "r"(a[2]), "r"(a[3]), "r"(b[0]), "r"(b[1]));
}
__device__ __forceinline__ uint32_t s2u(const void* p){
    uint32_t a;
    asm("{ .reg .u64 t; cvta.to.shared.u64 t, %1; cvt.u32.u64 %0, t; }" : "=r"(a) : "l"(p));
    return a;
}
__device__ __forceinline__ void cp16(uint32_t d, const void* g){
    asm volatile("cp.async.cg.shared.global [%0], [%1], 16;" :: "r"(d), "l"(g));
}
// packed f32x2 ops
__device__ __forceinline__ uint64_t pk2(float x, float y){
    uint64_t r; asm("mov.b64 %0, {%1,%2};" : "=l"(r) : "f"(x), "f"(y)); return r;
}
__device__ __forceinline__ void upk2(uint64_t v, float& x, float& y){
    asm("mov.b64 {%0,%1}, %2;" : "=f"(x), "=f"(y) : "l"(v));
}
__device__ __forceinline__ uint64_t mul2(uint64_t a, uint64_t b){
    uint64_t r; asm("mul.rn.f32x2 %0, %1, %2;" : "=l"(r) : "l"(a), "l"(b)); return r;
}
__device__ __forceinline__ uint64_t fma2(uint64_t a, uint64_t b, uint64_t c){
    uint64_t r; asm("fma.rn.f32x2 %0, %1, %2, %3;" : "=l"(r) : "l"(a), "l"(b), "l"(c)); return r;
}
__device__ __forceinline__ uint64_t add2(uint64_t a, uint64_t b){
    uint64_t r; asm("add.rn.f32x2 %0, %1, %2;" : "=l"(r) : "l"(a), "l"(b)); return r;
}

// ---------------- tf32 pre-round, all four operands in one launch ----------------
// block ranges: [0,4096) H ; [4096,20480) Wqkv ; [20480,28672) Wz ; [28672,36864) Wo
__global__ void round_all_kernel(
    const float* __restrict__ H, const float* __restrict__ Wq,
    const float* __restrict__ Wz, const float* __restrict__ Wo,
    float* __restrict__ oh, float* __restrict__ owq,
    float* __restrict__ owz, float* __restrict__ owo)
{
    int b = blockIdx.x;
    const float* src; float* dst; int off;
    if (b < 4096)       { src = H;  dst = oh;  off = b; }
    else if (b < 20480) { src = Wq; dst = owq; off = b - 4096; }
    else if (b < 28672) { src = Wz; dst = owz; off = b - 20480; }
    else                { src = Wo; dst = owo; off = b - 28672; }
    int i = off * 256 + threadIdx.x;
    float4 v = ((const float4*)src)[i];
    ((float4*)dst)[i] = make_float4(tf32r(v.x), tf32r(v.y), tf32r(v.z), tf32r(v.w));
}

// ================= tf32 mma.sync GEMM core (K-chunk 32, 4-stage pipeline) =================
// CTA 128x128, 256 thr (8 warps 4x2, warp tile 32x64).
#define FSWZ(r) (((((r) & 1) << 2)) | (((r) >> 1) & 3))
#define GK_SMEM (4 * 32768)

#define ISSUE(c, slot) { \
    uint32_t dA = sbase + (slot) * 32768; \
    _Pragma("unroll") for (int j = 0; j < 4; j++){ \
        int s = tid + j * 256; int row = s >> 3, u = s & 7; \
        cp16(dA + (uint32_t)(row * 8 + (u ^ FSWZ(row))) * 16, \
             Ab + (size_t)row * K + ((c) << 5) + (u << 2)); } \
    uint32_t dB = dA + 16384; \
    _Pragma("unroll") for (int j = 0; j < 4; j++){ \
        int s = tid + j * 256; int row = s >> 3, u = s & 7; \
        cp16(dB + (uint32_t)(row * 8 + (u ^ FSWZ(row))) * 16, \
             Bb + (size_t)row * K + ((c) << 5) + (u << 2)); } \
    asm volatile("cp.async.commit_group;" ::: "memory"); }

#define CHUNK(slot) { \
    const float4* AS = sm4 + (slot) * 2048; \
    const float4* BS = AS + 1024; \
    _Pragma("unroll") for (int kh = 0; kh < 2; kh++) { \
        const int u = tig + (kh << 2); \
        float4 af0[2], af1[2], bf[8]; \
        _Pragma("unroll") for (int mt = 0; mt < 2; mt++) { \
            int r0 = wm * 32 + mt * 16 + gid; \
            af0[mt] = AS[r0 * 8 + (u ^ FSWZ(r0))]; \
            af1[mt] = AS[(r0 + 8) * 8 + (u ^ FSWZ(r0 + 8))]; } \
        _Pragma("unroll") for (int nt = 0; nt < 8; nt++) { \
            int rn = wn * 64 + nt * 8 + gid; \
            bf[nt] = BS[rn * 8 + (u ^ FSWZ(rn))]; } \
        _Pragma("unroll") for (int mt = 0; mt < 2; mt++) { \
            uint32_t aa[4] = { __float_as_uint(af0[mt].x), __float_as_uint(af1[mt].x), \
                               __float_as_uint(af0[mt].y), __float_as_uint(af1[mt].y) }; \
            uint32_t ab[4] = { __float_as_uint(af0[mt].z), __float_as_uint(af1[mt].z), \
                               __float_as_uint(af0[mt].w), __float_as_uint(af1[mt].w) }; \
            _Pragma("unroll") for (int nt = 0; nt < 8; nt++) { \
                uint32_t ba[2] = { __float_as_uint(bf[nt].x), __float_as_uint(bf[nt].y) }; \
                uint32_t bb[2] = { __float_as_uint(bf[nt].z), __float_as_uint(bf[nt].w) }; \
                mma_tf32(acc[mt][nt], aa, ba); \
                mma_tf32(acc[mt][nt], ab, bb); } } } }

#define GEMM_BODY(KCONST) \
    const int K = (KCONST); \
    extern __shared__ __align__(16) float4 sm4[]; \
    const int tid  = threadIdx.x; \
    const int wid  = tid >> 5, lane = tid & 31; \
    const int wm   = wid & 3,  wn   = wid >> 2; \
    const int gid  = lane >> 2, tig = lane & 3; \
    const int NC = K >> 5; \
    const uint32_t sbase = s2u(sm4); \
    float acc[2][8][4]; \
    _Pragma("unroll") for (int i = 0; i < 2; i++) \
        _Pragma("unroll") for (int j = 0; j < 8; j++) \
            _Pragma("unroll") for (int r = 0; r < 4; r++) acc[i][j][r] = 0.f; \
    ISSUE(0, 0); \
    ISSUE(1, 1); \
    ISSUE(2, 2); \
    for (int c = 0; c < NC; c++) { \
        asm volatile("cp.async.wait_group 2;" ::: "memory"); \
        __syncthreads(); \
        if (c + 3 < NC) { ISSUE(c + 3, (c + 3) & 3); } \
        else { asm volatile("cp.async.commit_group;" ::: "memory"); } \
        CHUNK(c & 3); \
    } \
    _Pragma("unroll") for (int mt = 0; mt < 2; mt++) \
        _Pragma("unroll") for (int nt = 0; nt < 8; nt++) { \
            int r0 = wm * 32 + mt * 16 + gid; \
            int c0 = wn * 64 + nt * 8 + tig * 2; \
            *(float2*)&Cb[(size_t)(mrow + r0)     * ldC + c0] = make_float2(acc[mt][nt][0], acc[mt][nt][1]); \
            *(float2*)&Cb[(size_t)(mrow + r0 + 8) * ldC + c0] = make_float2(acc[mt][nt][2], acc[mt][nt][3]); }

// fused qkv+z projection: grid.x = 96 tiles (64 -> mixed, 32 -> z)
__global__ __launch_bounds__(256) void gemm_qkvz(
    const float* __restrict__ A, const float* __restrict__ B1, const float* __restrict__ B2,
    float* __restrict__ C1, float* __restrict__ C2)
{
    const int bx = blockIdx.x;
    const float* Ab = A + (size_t)blockIdx.y * 128 * HID;
    const float* Bb; float* Cb; int ldC;
    if (bx < 64) { Bb = B1 + (size_t)bx * 128 * HID;        Cb = C1 + bx * 128;        ldC = QKVT; }
    else         { Bb = B2 + (size_t)(bx - 64) * 128 * HID; Cb = C2 + (bx - 64) * 128; ldC = VTOT; }
    const int mrow = blockIdx.y * 128;
    GEMM_BODY(HID)
}

// out projection: C[M, HID] = A[M, VTOT] * B[HID, VTOT]^T
__global__ __launch_bounds__(256) void gemm_out(
    const float* __restrict__ A, const float* __restrict__ B, float* __restrict__ C)
{
    const float* Ab = A + (size_t)blockIdx.y * 128 * VTOT;
    const float* Bb = B + (size_t)blockIdx.x * 128 * VTOT;
    float* Cb = C + blockIdx.x * 128;
    const int ldC = HID;
    const int mrow = blockIdx.y * 128;
    GEMM_BODY(VTOT)
}

// ---------------- gating: a,b projections + fused gdn gating (transposed out [32][T]) --------
__global__ __launch_bounds__(256) void gating_kernel(
    const float* __restrict__ H, const float* __restrict__ Wa, const float* __restrict__ Wb,
    const float* __restrict__ A_log, const float* __restrict__ dtb,
    float* __restrict__ egT, float* __restrict__ betaT)
{
    __shared__ float hs[4][HID];
    const int t0 = blockIdx.x * 4;
    const int tid = threadIdx.x;
    for (int i = tid; i < 4 * HID; i += 256)
        hs[i >> 11][i & (HID - 1)] = H[(size_t)(t0 + (i >> 11)) * HID + (i & (HID - 1))];
    __syncthreads();
    const int wid = tid >> 5, lane = tid & 31;
    for (int hh = 0; hh < 4; hh++) {
        int h = wid * 4 + hh;
        float aa[4] = {0,0,0,0}, bb[4] = {0,0,0,0};
        for (int i = lane; i < HID; i += 32) {
            float wa = Wa[h * HID + i], wb = Wb[h * HID + i];
            #pragma unroll
            for (int tt = 0; tt < 4; tt++) {
                float x = hs[tt][i];
                aa[tt] += x * wa; bb[tt] += x * wb;
            }
        }
        #pragma unroll
        for (int off = 16; off; off >>= 1) {
            #pragma unroll
            for (int tt = 0; tt < 4; tt++) {
                aa[tt] += __shfl_xor_sync(0xffffffffu, aa[tt], off);
                bb[tt] += __shfl_xor_sync(0xffffffffu, bb[tt], off);
            }
        }
        if (lane < 4) {
            int tt = lane;
            float x  = aa[tt] + dtb[h];
            float sp = (x > 15.f) ? x : log1pf(expf(x));
            float g  = -expf(A_log[h]) * sp;
            egT  [h * T_LEN + t0 + tt] = expf(g);
            betaT[h * T_LEN + t0 + tt] = 1.f / (1.f + expf(-bb[tt]));
        }
    }
}

// ---------------- fused depthwise causal conv (K=4) + SiLU + qk l2norm ----------------
__global__ __launch_bounds__(256) void convnorm_kernel(
    const float* __restrict__ x, const float* __restrict__ w, float* __restrict__ y)
{
    const int wid = threadIdx.x >> 5, lane = threadIdx.x & 31;
    const int g = blockIdx.x * 8 + wid;
    const int t = g >> 6, s = g & 63;
    const int c0 = s * 128 + lane * 4;

    float4 w0 = *(const float4*)(w + (size_t)(c0 + 0) * 4);
    float4 w1 = *(const float4*)(w + (size_t)(c0 + 1) * 4);
    float4 w2 = *(const float4*)(w + (size_t)(c0 + 2) * 4);
    float4 w3 = *(const float4*)(w + (size_t)(c0 + 3) * 4);

    const float* xb = x + (size_t)t * QKVT + c0;
    float4 zz = make_float4(0.f, 0.f, 0.f, 0.f);
    float4 x0 = *(const float4*)xb;
    float4 x1 = (t >= 1) ? *(const float4*)(xb -     QKVT) : zz;
    float4 x2 = (t >= 2) ? *(const float4*)(xb - 2 * QKVT) : zz;
    float4 x3 = (t >= 3) ? *(const float4*)(xb - 3 * QKVT) : zz;

    float a0 = x0.x * w0.w + x1.x * w0.z + x2.x * w0.y + x3.x * w0.x;
    float a1 = x0.y * w1.w + x1.y * w1.z + x2.y * w1.y + x3.y * w1.x;
    float a2 = x0.z * w2.w + x1.z * w2.z + x2.z * w2.y + x3.z * w2.x;
    float a3 = x0.w * w3.w + x1.w * w3.z + x2.w * w3.y + x3.w * w3.x;
    a0 = a0 / (1.f + expf(-a0));
    a1 = a1 / (1.f + expf(-a1));
    a2 = a2 / (1.f + expf(-a2));
    a3 = a3 / (1.f + expf(-a3));

    if (s < 32) {
        float ss = a0*a0 + a1*a1 + a2*a2 + a3*a3;
        #pragma unroll
        for (int off = 16; off; off >>= 1) ss += __shfl_xor_sync(0xffffffffu, ss, off);
        float inv = rsqrtf(ss + 1e-6f);
        if (s < 16) inv *= 0.08838834764831843f;   // q * 128^-0.5
        a0 *= inv; a1 *= inv; a2 *= inv; a3 *= inv;
    }
    *(float4*)(y + (size_t)t * QKVT + c0) = make_float4(a0, a1, a2, a3);
}

// ---------------- gated delta-rule recurrence: cp.async ring, R10-proven form ----------------
// grid 128: CTA = (head hv, Dv slice of 32). 128 threads: warp = 32 k-rows, lane = v-col.
__global__ __launch_bounds__(128) void recurrence_kernel(
    const float* __restrict__ conv, const float* __restrict__ egT,
    const float* __restrict__ betaT, float* __restrict__ o)
{
    const int hv    = blockIdx.x >> 2;
    const int vbase = (blockIdx.x & 3) * 32;
    const int kh    = hv >> 1;
    const int tid   = threadIdx.x, wid = tid >> 5, lane = tid & 31;

    __shared__ __align__(16) float rk[4][128];
    __shared__ __align__(16) float rq[4][128];
    __shared__ __align__(16) float rv[4][32];
    __shared__ float p1[4][32], p2[4][32];
    __shared__ float egs[T_LEN], bets[T_LEN];

    for (int i = tid; i < T_LEN; i += 128) {
        egs[i]  = egT  [hv * T_LEN + i];
        bets[i] = betaT[hv * T_LEN + i];
    }

    uint64_t S2[16];
    #pragma unroll
    for (int i = 0; i < 16; i++) S2[i] = 0ull;

    const uint32_t rkb = s2u(rk), rqb = s2u(rq), rvb = s2u(rv);

#define RISSUE(tt) { \
    const int sl = (tt) & 3; \
    const float* base = conv + (size_t)(tt) * QKVT; \
    if (tid < 32)      cp16(rkb + sl * 512 + tid * 16,        base + 2048 + kh * 128 + tid * 4); \
    else if (tid < 64) cp16(rqb + sl * 512 + (tid - 32) * 16, base +        kh * 128 + (tid - 32) * 4); \
    else if (tid < 72) cp16(rvb + sl * 128 + (tid - 64) * 16, base + 4096 + hv * 128 + vbase + (tid - 64) * 4); \
    asm volatile("cp.async.commit_group;" ::: "memory"); }

    RISSUE(0); RISSUE(1); RISSUE(2);
    asm volatile("cp.async.wait_group 2;" ::: "memory");
    __syncthreads();                               // slot 0 ready + gates visible

    for (int t = 0; t < T_LEN; t++) {
        const int s = t & 3;
        if (t + 3 < T_LEN) { RISSUE(t + 3); }
        else { asm volatile("cp.async.commit_group;" ::: "memory"); }

        const uint32_t ka = rkb + s * 512 + wid * 128;
        const uint32_t qa = rqb + s * 512 + wid * 128;
        float vcur = rv[s][lane];
        float egc = egs[t], bc = bets[t];

        uint64_t kp[16];
        #pragma unroll
        for (int i = 0; i < 8; i++)
            asm volatile("ld.shared.v2.b64 {%0,%1}, [%2];"
                : "=l"(kp[2*i]), "=l"(kp[2*i+1]) : "r"(ka + i * 16));
        uint64_t eg2 = pk2(egc, egc);
        uint64_t acA = 0ull, acB = 0ull, acC = 0ull, acD = 0ull;
        #pragma unroll
        for (int i = 0; i < 4; i++) {
            S2[4*i]   = mul2(S2[4*i],   eg2);  acA = fma2(kp[4*i],   S2[4*i],   acA);
            S2[4*i+1] = mul2(S2[4*i+1], eg2);  acB = fma2(kp[4*i+1], S2[4*i+1], acB);
            S2[4*i+2] = mul2(S2[4*i+2], eg2);  acC = fma2(kp[4*i+2], S2[4*i+2], acC);
            S2[4*i+3] = mul2(S2[4*i+3], eg2);  acD = fma2(kp[4*i+3], S2[4*i+3], acD);
        }
        float ax, ay;
        upk2(add2(add2(acA, acB), add2(acC, acD)), ax, ay);
        p1[wid][lane] = ax + ay;
        uint64_t qp[16];
        #pragma unroll
        for (int i = 0; i < 8; i++)
            asm volatile("ld.shared.v2.b64 {%0,%1}, [%2];"
                : "=l"(qp[2*i]), "=l"(qp[2*i+1]) : "r"(qa + i * 16));
        __syncthreads();                                   // bar1: p1 ready
        float pred  = (p1[0][lane] + p1[1][lane]) + (p1[2][lane] + p1[3][lane]);
        float delta = bc * (vcur - pred);
        uint64_t d2 = pk2(delta, delta);
        uint64_t oA = 0ull, oB = 0ull, oC = 0ull, oD = 0ull;
        #pragma unroll
        for (int i = 0; i < 4; i++) {
            S2[4*i]   = fma2(kp[4*i],   d2, S2[4*i]);    oA = fma2(qp[4*i],   S2[4*i],   oA);
            S2[4*i+1] = fma2(kp[4*i+1], d2, S2[4*i+1]);  oB = fma2(qp[4*i+1], S2[4*i+1], oB);
            S2[4*i+2] = fma2(kp[4*i+2], d2, S2[4*i+2]);  oC = fma2(qp[4*i+2], S2[4*i+2], oC);
            S2[4*i+3] = fma2(kp[4*i+3], d2, S2[4*i+3]);  oD = fma2(qp[4*i+3], S2[4*i+3], oD);
        }
        upk2(add2(add2(oA, oB), add2(oC, oD)), ax, ay);
        p2[wid][lane] = ax + ay;
        asm volatile("cp.async.wait_group 2;" ::: "memory");  // next slot landed
        __syncthreads();                                   // bar2: p2 ready + slot visible
        if (wid == 0)
            o[(size_t)t * VTOT + hv * 128 + vbase + lane] =
                (p2[0][lane] + p2[1][lane]) + (p2[2][lane] + p2[3][lane]);
    }
}

// ---------------- gated RMSNorm * silu(z), writes tf32-rounded (in place on o) ----------------
__global__ void gated_norm_kernel(float* __restrict__ o, const float* __restrict__ z,
                                  const float* __restrict__ nw)
{
    int g = blockIdx.x * 8 + (threadIdx.x >> 5);
    int lane = threadIdx.x & 31;
    size_t base = (size_t)g * 128;
    float x0 = o[base+lane], x1 = o[base+lane+32], x2 = o[base+lane+64], x3 = o[base+lane+96];
    float ss = x0*x0 + x1*x1 + x2*x2 + x3*x3;
    #pragma unroll
    for (int off = 16; off; off >>= 1) ss += __shfl_xor_sync(0xffffffffu, ss, off);
    float r = rsqrtf(ss * (1.f / 128.f) + 1e-6f);
    #pragma unroll
    for (int j = 0; j < 4; j++) {
        int d = lane + 32 * j;
        float x = (j == 0 ? x0 : j == 1 ? x1 : j == 2 ? x2 : x3);
        float zz = z[base + d];
        o[base + d] = tf32r(x * r * nw[d] * (zz / (1.f + expf(-zz))));
    }
}

// ---------------- launch ----------------
extern "C" void kernel_launch(void* const* d_in, const int* in_sizes, int n_in,
                              void* d_out, int out_size)
{
    const float* H     = (const float*)d_in[0];
    const float* Wqkv  = (const float*)d_in[1];
    const float* Wz    = (const float*)d_in[2];
    const float* Wa    = (const float*)d_in[3];
    const float* Wb    = (const float*)d_in[4];
    const float* Wc    = (const float*)d_in[5];
    const float* Wo    = (const float*)d_in[6];
    const float* nw    = (const float*)d_in[7];
    const float* A_log = (const float*)d_in[8];
    const float* dtb   = (const float*)d_in[9];
    float* out = (float*)d_out;

    float *mixed, *conv, *z, *o, *eg, *beta, *ht, *wq, *wz, *wo;
    cudaGetSymbolAddress((void**)&mixed, g_mixed);
    cudaGetSymbolAddress((void**)&conv,  g_conv);
    cudaGetSymbolAddress((void**)&z,     g_z);
    cudaGetSymbolAddress((void**)&o,     g_o);
    cudaGetSymbolAddress((void**)&eg,    g_eg);
    cudaGetSymbolAddress((void**)&beta,  g_beta);
    cudaGetSymbolAddress((void**)&ht,    g_h);
    cudaGetSymbolAddress((void**)&wq,    g_wq);
    cudaGetSymbolAddress((void**)&wz,    g_wz);
    cudaGetSymbolAddress((void**)&wo,    g_wo);

    cudaFuncSetAttribute(gemm_qkvz, cudaFuncAttributeMaxDynamicSharedMemorySize, GK_SMEM);
    cudaFuncSetAttribute(gemm_out,  cudaFuncAttributeMaxDynamicSharedMemorySize, GK_SMEM);

    round_all_kernel<<<36864, 256>>>(H, Wqkv, Wz, Wo, ht, wq, wz, wo);                     // 1
    gemm_qkvz<<<dim3(96, T_LEN / 128), 256, GK_SMEM>>>(ht, wq, wz, mixed, z);              // 2
    gating_kernel<<<T_LEN / 4, 256>>>(H, Wa, Wb, A_log, dtb, eg, beta);                    // 3
    convnorm_kernel<<<T_LEN * 64 / 8, 256>>>(mixed, Wc, conv);                             // 4 <- profiled
    recurrence_kernel<<<128, 128>>>(conv, eg, beta, o);                                    // 5
    gated_norm_kernel<<<T_LEN * 32 / 8, 256>>>(o, z, nw);                                  // 6
    gemm_out<<<dim3(HID / 128, T_LEN / 128), 256, GK_SMEM>>>(o, wo, out);                  // 7
}

// round 16
// speedup vs baseline: 1.6776x; 1.6776x over previous
#include <cuda_runtime.h>
#include <cstdint>
#include <math.h>

#define T_LEN 2048
#define HID   2048
#define QKVT  8192
#define VTOT  4096
#define NHV   32
#define NHK   16

// ---------------- scratch (device globals; no allocation allowed) ----------------
__device__ float g_mixed[16777216];   // [T, 8192]  qkv-proj out
__device__ float g_conv [16777216];   // [T, 8192]  conv+silu(+l2norm) out
__device__ float g_z    [ 8388608];   // [T, 4096]
__device__ float g_o    [ 8388608];   // [T, 32, 128]
__device__ float g_eg   [NHV*T_LEN];  // transposed: [32][T]
__device__ float g_beta [NHV*T_LEN];  // transposed: [32][T]
// tf32-prerounded operands
__device__ float g_h  [ 4194304];     // [2048, 2048]
__device__ float g_wq [16777216];     // [8192, 2048]
__device__ float g_wz [ 8388608];     // [4096, 2048]
__device__ float g_wo [ 8388608];     // [2048, 4096]

// ---------------- helpers ----------------
__device__ __forceinline__ float tf32r(float x){
    uint32_t u; asm("cvt.rna.tf32.f32 %0, %1;" : "=r"(u) : "f"(x));
    return __uint_as_float(u);
}
__device__ __forceinline__ void mma_tf32(float* c, const uint32_t* a, const uint32_t* b){
    asm volatile("mma.sync.aligned.m16n8k8.row.col.f32.tf32.tf32.f32 "
        "{%0,%1,%2,%3}, {%4,%5,%6,%7}, {%8,%9}, {%0,%1,%2,%3};\n"
        : "+f"(c[0]), "+f"(c[1]), "+f"(c[2]), "+f"(c[3])
        : "r"(a[0]), "r"(a[1]), "r"(a[2]), "r"(a[3]), "r"(b[0]), "r"(b[1]));
}
__device__ __forceinline__ uint32_t s2u(const void* p){
    uint32_t a;
    asm("{ .reg .u64 t; cvta.to.shared.u64 t, %1; cvt.u32.u64 %0, t; }" : "=r"(a) : "l"(p));
    return a;
}
__device__ __forceinline__ void cp16(uint32_t d, const void* g){
    asm volatile("cp.async.cg.shared.global [%0], [%1], 16;" :: "r"(d), "l"(g));
}
// packed f32x2 ops
__device__ __forceinline__ uint64_t pk2(float x, float y){
    uint64_t r; asm("mov.b64 %0, {%1,%2};" : "=l"(r) : "f"(x), "f"(y)); return r;
}
__device__ __forceinline__ void upk2(uint64_t v, float& x, float& y){
    asm("mov.b64 {%0,%1}, %2;" : "=f"(x), "=f"(y) : "l"(v));
}
__device__ __forceinline__ uint64_t mul2(uint64_t a, uint64_t b){
    uint64_t r; asm("mul.rn.f32x2 %0, %1, %2;" : "=l"(r) : "l"(a), "l"(b)); return r;
}
__device__ __forceinline__ uint64_t fma2(uint64_t a, uint64_t b, uint64_t c){
    uint64_t r; asm("fma.rn.f32x2 %0, %1, %2, %3;" : "=l"(r) : "l"(a), "l"(b), "l"(c)); return r;
}
__device__ __forceinline__ uint64_t add2(uint64_t a, uint64_t b){
    uint64_t r; asm("add.rn.f32x2 %0, %1, %2;" : "=l"(r) : "l"(a), "l"(b)); return r;
}

// ---------------- tf32 pre-round, all four operands in one launch ----------------
// block ranges: [0,4096) H ; [4096,20480) Wqkv ; [20480,28672) Wz ; [28672,36864) Wo
__global__ void round_all_kernel(
    const float* __restrict__ H, const float* __restrict__ Wq,
    const float* __restrict__ Wz, const float* __restrict__ Wo,
    float* __restrict__ oh, float* __restrict__ owq,
    float* __restrict__ owz, float* __restrict__ owo)
{
    int b = blockIdx.x;
    const float* src; float* dst; int off;
    if (b < 4096)       { src = H;  dst = oh;  off = b; }
    else if (b < 20480) { src = Wq; dst = owq; off = b - 4096; }
    else if (b < 28672) { src = Wz; dst = owz; off = b - 20480; }
    else                { src = Wo; dst = owo; off = b - 28672; }
    int i = off * 256 + threadIdx.x;
    float4 v = ((const float4*)src)[i];
    ((float4*)dst)[i] = make_float4(tf32r(v.x), tf32r(v.y), tf32r(v.z), tf32r(v.w));
}

// ================= tf32 mma.sync GEMM core (R8/R13-proven form) =================
// CTA 128x128, K-chunk 32, 256 thr (8 warps 4x2, warp tile 32x64). 3-stage cp.async pipeline.
#define FSWZ(r) (((((r) & 1) << 2)) | (((r) >> 1) & 3))
#define GK_SMEM (3 * 32768)

#define ISSUE(c, slot) { \
    uint32_t dA = sbase + (slot) * 32768; \
    _Pragma("unroll") for (int j = 0; j < 4; j++){ \
        int s = tid + j * 256; int row = s >> 3, u = s & 7; \
        cp16(dA + (uint32_t)(row * 8 + (u ^ FSWZ(row))) * 16, \
             Ab + (size_t)row * K + ((c) << 5) + (u << 2)); } \
    uint32_t dB = dA + 16384; \
    _Pragma("unroll") for (int j = 0; j < 4; j++){ \
        int s = tid + j * 256; int row = s >> 3, u = s & 7; \
        cp16(dB + (uint32_t)(row * 8 + (u ^ FSWZ(row))) * 16, \
             Bb + (size_t)row * K + ((c) << 5) + (u << 2)); } \
    asm volatile("cp.async.commit_group;" ::: "memory"); }

#define CHUNK(slot) { \
    const float4* AS = sm4 + (slot) * 2048; \
    const float4* BS = AS + 1024; \
    _Pragma("unroll") for (int kh = 0; kh < 2; kh++) { \
        const int u = tig + (kh << 2); \
        float4 af0[2], af1[2], bf[8]; \
        _Pragma("unroll") for (int mt = 0; mt < 2; mt++) { \
            int r0 = wm * 32 + mt * 16 + gid; \
            af0[mt] = AS[r0 * 8 + (u ^ FSWZ(r0))]; \
            af1[mt] = AS[(r0 + 8) * 8 + (u ^ FSWZ(r0 + 8))]; } \
        _Pragma("unroll") for (int nt = 0; nt < 8; nt++) { \
            int rn = wn * 64 + nt * 8 + gid; \
            bf[nt] = BS[rn * 8 + (u ^ FSWZ(rn))]; } \
        _Pragma("unroll") for (int mt = 0; mt < 2; mt++) { \
            uint32_t aa[4] = { __float_as_uint(af0[mt].x), __float_as_uint(af1[mt].x), \
                               __float_as_uint(af0[mt].y), __float_as_uint(af1[mt].y) }; \
            uint32_t ab[4] = { __float_as_uint(af0[mt].z), __float_as_uint(af1[mt].z), \
                               __float_as_uint(af0[mt].w), __float_as_uint(af1[mt].w) }; \
            _Pragma("unroll") for (int nt = 0; nt < 8; nt++) { \
                uint32_t ba[2] = { __float_as_uint(bf[nt].x), __float_as_uint(bf[nt].y) }; \
                uint32_t bb[2] = { __float_as_uint(bf[nt].z), __float_as_uint(bf[nt].w) }; \
                mma_tf32(acc[mt][nt], aa, ba); \
                mma_tf32(acc[mt][nt], ab, bb); } } } }

#define GEMM_BODY(KCONST) \
    const int K = (KCONST); \
    extern __shared__ __align__(16) float4 sm4[]; \
    const int tid  = threadIdx.x; \
    const int wid  = tid >> 5, lane = tid & 31; \
    const int wm   = wid & 3,  wn   = wid >> 2; \
    const int gid  = lane >> 2, tig = lane & 3; \
    const int NC = K >> 5; \
    const uint32_t sbase = s2u(sm4); \
    float acc[2][8][4]; \
    _Pragma("unroll") for (int i = 0; i < 2; i++) \
        _Pragma("unroll") for (int j = 0; j < 8; j++) \
            _Pragma("unroll") for (int r = 0; r < 4; r++) acc[i][j][r] = 0.f; \
    ISSUE(0, 0); \
    ISSUE(1, 1); \
    for (int c = 0; c < NC; c++) { \
        asm volatile("cp.async.wait_group 1;" ::: "memory"); \
        __syncthreads(); \
        if (c + 2 < NC) { ISSUE(c + 2, (c + 2) % 3); } \
        else { asm volatile("cp.async.commit_group;" ::: "memory"); } \
        CHUNK(c % 3); \
    } \
    _Pragma("unroll") for (int mt = 0; mt < 2; mt++) \
        _Pragma("unroll") for (int nt = 0; nt < 8; nt++) { \
            int r0 = wm * 32 + mt * 16 + gid; \
            int c0 = wn * 64 + nt * 8 + tig * 2; \
            *(float2*)&Cb[(size_t)(mrow + r0)     * ldC + c0] = make_float2(acc[mt][nt][0], acc[mt][nt][1]); \
            *(float2*)&Cb[(size_t)(mrow + r0 + 8) * ldC + c0] = make_float2(acc[mt][nt][2], acc[mt][nt][3]); }

// fused qkv+z projection: grid.x = 96 tiles (64 -> mixed, 32 -> z)
__global__ __launch_bounds__(256) void gemm_qkvz(
    const float* __restrict__ A, const float* __restrict__ B1, const float* __restrict__ B2,
    float* __restrict__ C1, float* __restrict__ C2)
{
    const int bx = blockIdx.x;
    const float* Ab = A + (size_t)blockIdx.y * 128 * HID;
    const float* Bb; float* Cb; int ldC;
    if (bx < 64) { Bb = B1 + (size_t)bx * 128 * HID;        Cb = C1 + bx * 128;        ldC = QKVT; }
    else         { Bb = B2 + (size_t)(bx - 64) * 128 * HID; Cb = C2 + (bx - 64) * 128; ldC = VTOT; }
    const int mrow = blockIdx.y * 128;
    GEMM_BODY(HID)
}

// out projection: C[M, HID] = A[M, VTOT] * B[HID, VTOT]^T
__global__ __launch_bounds__(256) void gemm_out(
    const float* __restrict__ A, const float* __restrict__ B, float* __restrict__ C)
{
    const float* Ab = A + (size_t)blockIdx.y * 128 * VTOT;
    const float* Bb = B + (size_t)blockIdx.x * 128 * VTOT;
    float* Cb = C + blockIdx.x * 128;
    const int ldC = HID;
    const int mrow = blockIdx.y * 128;
    GEMM_BODY(VTOT)
}

// ---------------- gating: a,b projections + fused gdn gating (transposed out [32][T]) --------
__global__ __launch_bounds__(256) void gating_kernel(
    const float* __restrict__ H, const float* __restrict__ Wa, const float* __restrict__ Wb,
    const float* __restrict__ A_log, const float* __restrict__ dtb,
    float* __restrict__ egT, float* __restrict__ betaT)
{
    __shared__ float hs[4][HID];
    const int t0 = blockIdx.x * 4;
    const int tid = threadIdx.x;
    for (int i = tid; i < 4 * HID; i += 256)
        hs[i >> 11][i & (HID - 1)] = H[(size_t)(t0 + (i >> 11)) * HID + (i & (HID - 1))];
    __syncthreads();
    const int wid = tid >> 5, lane = tid & 31;
    for (int hh = 0; hh < 4; hh++) {
        int h = wid * 4 + hh;
        float aa[4] = {0,0,0,0}, bb[4] = {0,0,0,0};
        for (int i = lane; i < HID; i += 32) {
            float wa = Wa[h * HID + i], wb = Wb[h * HID + i];
            #pragma unroll
            for (int tt = 0; tt < 4; tt++) {
                float x = hs[tt][i];
                aa[tt] += x * wa; bb[tt] += x * wb;
            }
        }
        #pragma unroll
        for (int off = 16; off; off >>= 1) {
            #pragma unroll
            for (int tt = 0; tt < 4; tt++) {
                aa[tt] += __shfl_xor_sync(0xffffffffu, aa[tt], off);
                bb[tt] += __shfl_xor_sync(0xffffffffu, bb[tt], off);
            }
        }
        if (lane < 4) {
            int tt = lane;
            float x  = aa[tt] + dtb[h];
            float sp = (x > 15.f) ? x : log1pf(expf(x));
            float g  = -expf(A_log[h]) * sp;
            egT  [h * T_LEN + t0 + tt] = expf(g);
            betaT[h * T_LEN + t0 + tt] = 1.f / (1.f + expf(-bb[tt]));
        }
    }
}

// ---------------- fused depthwise causal conv (K=4) + SiLU + qk l2norm ----------------
__global__ __launch_bounds__(256) void convnorm_kernel(
    const float* __restrict__ x, const float* __restrict__ w, float* __restrict__ y)
{
    const int wid = threadIdx.x >> 5, lane = threadIdx.x & 31;
    const int g = blockIdx.x * 8 + wid;
    const int t = g >> 6, s = g & 63;
    const int c0 = s * 128 + lane * 4;

    float4 w0 = *(const float4*)(w + (size_t)(c0 + 0) * 4);
    float4 w1 = *(const float4*)(w + (size_t)(c0 + 1) * 4);
    float4 w2 = *(const float4*)(w + (size_t)(c0 + 2) * 4);
    float4 w3 = *(const float4*)(w + (size_t)(c0 + 3) * 4);

    const float* xb = x + (size_t)t * QKVT + c0;
    float4 zz = make_float4(0.f, 0.f, 0.f, 0.f);
    float4 x0 = *(const float4*)xb;
    float4 x1 = (t >= 1) ? *(const float4*)(xb -     QKVT) : zz;
    float4 x2 = (t >= 2) ? *(const float4*)(xb - 2 * QKVT) : zz;
    float4 x3 = (t >= 3) ? *(const float4*)(xb - 3 * QKVT) : zz;

    float a0 = x0.x * w0.w + x1.x * w0.z + x2.x * w0.y + x3.x * w0.x;
    float a1 = x0.y * w1.w + x1.y * w1.z + x2.y * w1.y + x3.y * w1.x;
    float a2 = x0.z * w2.w + x1.z * w2.z + x2.z * w2.y + x3.z * w2.x;
    float a3 = x0.w * w3.w + x1.w * w3.z + x2.w * w3.y + x3.w * w3.x;
    a0 = a0 / (1.f + expf(-a0));
    a1 = a1 / (1.f + expf(-a1));
    a2 = a2 / (1.f + expf(-a2));
    a3 = a3 / (1.f + expf(-a3));

    if (s < 32) {
        float ss = a0*a0 + a1*a1 + a2*a2 + a3*a3;
        #pragma unroll
        for (int off = 16; off; off >>= 1) ss += __shfl_xor_sync(0xffffffffu, ss, off);
        float inv = rsqrtf(ss + 1e-6f);
        if (s < 16) inv *= 0.08838834764831843f;   // q * 128^-0.5
        a0 *= inv; a1 *= inv; a2 *= inv; a3 *= inv;
    }
    *(float4*)(y + (size_t)t * QKVT + c0) = make_float4(a0, a1, a2, a3);
}

// ---------------- gated delta-rule recurrence: cp.async ring, R10-proven form ----------------
// grid 128: CTA = (head hv, Dv slice of 32). 128 threads: warp = 32 k-rows, lane = v-col.
__global__ __launch_bounds__(128) void recurrence_kernel(
    const float* __restrict__ conv, const float* __restrict__ egT,
    const float* __restrict__ betaT, float* __restrict__ o)
{
    const int hv    = blockIdx.x >> 2;
    const int vbase = (blockIdx.x & 3) * 32;
    const int kh    = hv >> 1;
    const int tid   = threadIdx.x, wid = tid >> 5, lane = tid & 31;

    __shared__ __align__(16) float rk[4][128];
    __shared__ __align__(16) float rq[4][128];
    __shared__ __align__(16) float rv[4][32];
    __shared__ float p1[4][32], p2[4][32];
    __shared__ float egs[T_LEN], bets[T_LEN];

    for (int i = tid; i < T_LEN; i += 128) {
        egs[i]  = egT  [hv * T_LEN + i];
        bets[i] = betaT[hv * T_LEN + i];
    }

    uint64_t S2[16];
    #pragma unroll
    for (int i = 0; i < 16; i++) S2[i] = 0ull;

    const uint32_t rkb = s2u(rk), rqb = s2u(rq), rvb = s2u(rv);

#define RISSUE(tt) { \
    const int sl = (tt) & 3; \
    const float* base = conv + (size_t)(tt) * QKVT; \
    if (tid < 32)      cp16(rkb + sl * 512 + tid * 16,        base + 2048 + kh * 128 + tid * 4); \
    else if (tid < 64) cp16(rqb + sl * 512 + (tid - 32) * 16, base +        kh * 128 + (tid - 32) * 4); \
    else if (tid < 72) cp16(rvb + sl * 128 + (tid - 64) * 16, base + 4096 + hv * 128 + vbase + (tid - 64) * 4); \
    asm volatile("cp.async.commit_group;" ::: "memory"); }

    RISSUE(0); RISSUE(1); RISSUE(2);
    asm volatile("cp.async.wait_group 2;" ::: "memory");
    __syncthreads();                               // slot 0 ready + gates visible

    for (int t = 0; t < T_LEN; t++) {
        const int s = t & 3;
        if (t + 3 < T_LEN) { RISSUE(t + 3); }
        else { asm volatile("cp.async.commit_group;" ::: "memory"); }

        const uint32_t ka = rkb + s * 512 + wid * 128;
        const uint32_t qa = rqb + s * 512 + wid * 128;
        float vcur = rv[s][lane];
        float egc = egs[t], bc = bets[t];

        uint64_t kp[16];
        #pragma unroll
        for (int i = 0; i < 8; i++)
            asm volatile("ld.shared.v2.b64 {%0,%1}, [%2];"
                : "=l"(kp[2*i]), "=l"(kp[2*i+1]) : "r"(ka + i * 16));
        uint64_t eg2 = pk2(egc, egc);
        uint64_t acA = 0ull, acB = 0ull, acC = 0ull, acD = 0ull;
        #pragma unroll
        for (int i = 0; i < 4; i++) {
            S2[4*i]   = mul2(S2[4*i],   eg2);  acA = fma2(kp[4*i],   S2[4*i],   acA);
            S2[4*i+1] = mul2(S2[4*i+1], eg2);  acB = fma2(kp[4*i+1], S2[4*i+1], acB);
            S2[4*i+2] = mul2(S2[4*i+2], eg2);  acC = fma2(kp[4*i+2], S2[4*i+2], acC);
            S2[4*i+3] = mul2(S2[4*i+3], eg2);  acD = fma2(kp[4*i+3], S2[4*i+3], acD);
        }
        float ax, ay;
        upk2(add2(add2(acA, acB), add2(acC, acD)), ax, ay);
        p1[wid][lane] = ax + ay;
        uint64_t qp[16];
        #pragma unroll
        for (int i = 0; i < 8; i++)
            asm volatile("ld.shared.v2.b64 {%0,%1}, [%2];"
                : "=l"(qp[2*i]), "=l"(qp[2*i+1]) : "r"(qa + i * 16));
        __syncthreads();                                   // bar1: p1 ready
        float pred  = (p1[0][lane] + p1[1][lane]) + (p1[2][lane] + p1[3][lane]);
        float delta = bc * (vcur - pred);
        uint64_t d2 = pk2(delta, delta);
        uint64_t oA = 0ull, oB = 0ull, oC = 0ull, oD = 0ull;
        #pragma unroll
        for (int i = 0; i < 4; i++) {
            S2[4*i]   = fma2(kp[4*i],   d2, S2[4*i]);    oA = fma2(qp[4*i],   S2[4*i],   oA);
            S2[4*i+1] = fma2(kp[4*i+1], d2, S2[4*i+1]);  oB = fma2(qp[4*i+1], S2[4*i+1], oB);
            S2[4*i+2] = fma2(kp[4*i+2], d2, S2[4*i+2]);  oC = fma2(qp[4*i+2], S2[4*i+2], oC);
            S2[4*i+3] = fma2(kp[4*i+3], d2, S2[4*i+3]);  oD = fma2(qp[4*i+3], S2[4*i+3], oD);
        }
        upk2(add2(add2(oA, oB), add2(oC, oD)), ax, ay);
        p2[wid][lane] = ax + ay;
        asm volatile("cp.async.wait_group 2;" ::: "memory");  // next slot landed
        __syncthreads();                                   // bar2: p2 ready + slot visible
        if (wid == 0)
            o[(size_t)t * VTOT + hv * 128 + vbase + lane] =
                (p2[0][lane] + p2[1][lane]) + (p2[2][lane] + p2[3][lane]);
    }
}

// ---------------- gated RMSNorm * silu(z), writes tf32-rounded (in place on o) ----------------
__global__ void gated_norm_kernel(float* __restrict__ o, const float* __restrict__ z,
                                  const float* __restrict__ nw)
{
    int g = blockIdx.x * 8 + (threadIdx.x >> 5);
    int lane = threadIdx.x & 31;
    size_t base = (size_t)g * 128;
    float x0 = o[base+lane], x1 = o[base+lane+32], x2 = o[base+lane+64], x3 = o[base+lane+96];
    float ss = x0*x0 + x1*x1 + x2*x2 + x3*x3;
    #pragma unroll
    for (int off = 16; off; off >>= 1) ss += __shfl_xor_sync(0xffffffffu, ss, off);
    float r = rsqrtf(ss * (1.f / 128.f) + 1e-6f);
    #pragma unroll
    for (int j = 0; j < 4; j++) {
        int d = lane + 32 * j;
        float x = (j == 0 ? x0 : j == 1 ? x1 : j == 2 ? x2 : x3);
        float zz = z[base + d];
        o[base + d] = tf32r(x * r * nw[d] * (zz / (1.f + expf(-zz))));
    }
}

// ---------------- launch ----------------
extern "C" void kernel_launch(void* const* d_in, const int* in_sizes, int n_in,
                              void* d_out, int out_size)
{
    const float* H     = (const float*)d_in[0];
    const float* Wqkv  = (const float*)d_in[1];
    const float* Wz    = (const float*)d_in[2];
    const float* Wa    = (const float*)d_in[3];
    const float* Wb    = (const float*)d_in[4];
    const float* Wc    = (const float*)d_in[5];
    const float* Wo    = (const float*)d_in[6];
    const float* nw    = (const float*)d_in[7];
    const float* A_log = (const float*)d_in[8];
    const float* dtb   = (const float*)d_in[9];
    float* out = (float*)d_out;

    float *mixed, *conv, *z, *o, *eg, *beta, *ht, *wq, *wz, *wo;
    cudaGetSymbolAddress((void**)&mixed, g_mixed);
    cudaGetSymbolAddress((void**)&conv,  g_conv);
    cudaGetSymbolAddress((void**)&z,     g_z);
    cudaGetSymbolAddress((void**)&o,     g_o);
    cudaGetSymbolAddress((void**)&eg,    g_eg);
    cudaGetSymbolAddress((void**)&beta,  g_beta);
    cudaGetSymbolAddress((void**)&ht,    g_h);
    cudaGetSymbolAddress((void**)&wq,    g_wq);
    cudaGetSymbolAddress((void**)&wz,    g_wz);
    cudaGetSymbolAddress((void**)&wo,    g_wo);

    cudaFuncSetAttribute(gemm_qkvz, cudaFuncAttributeMaxDynamicSharedMemorySize, GK_SMEM);
    cudaFuncSetAttribute(gemm_out,  cudaFuncAttributeMaxDynamicSharedMemorySize, GK_SMEM);

    round_all_kernel<<<36864, 256>>>(H, Wqkv, Wz, Wo, ht, wq, wz, wo);                     // 1
    gemm_qkvz<<<dim3(96, T_LEN / 128), 256, GK_SMEM>>>(ht, wq, wz, mixed, z);              // 2
    gating_kernel<<<T_LEN / 4, 256>>>(H, Wa, Wb, A_log, dtb, eg, beta);                    // 3
    convnorm_kernel<<<T_LEN * 64 / 8, 256>>>(mixed, Wc, conv);                             // 4 <- profiled
    recurrence_kernel<<<128, 128>>>(conv, eg, beta, o);                                    // 5
    gated_norm_kernel<<<T_LEN * 32 / 8, 256>>>(o, z, nw);                                  // 6
    gemm_out<<<dim3(HID / 128, T_LEN / 128), 256, GK_SMEM>>>(o, wo, out);                  // 7
}